// round 2
// baseline (speedup 1.0000x reference)
#include <cuda_runtime.h>
#include <cuda_bf16.h>
#include <cstdint>

// Problem shapes (fixed by the dataset)
#define NUM_CLASSES 32000
#define EMBED_DIM   128
#define N_TOKENS    (64 * 4096)   // B*T = 262144

// Scratch: W^T with bias pre-added. 32000 * 128 * 4B = 16.384 MB.
// __device__ global (no allocation APIs allowed).
__device__ float g_Wt[NUM_CLASSES * EMBED_DIM];

// ---------------------------------------------------------------------------
// Kernel 1: Wt[c][d] = W[d][c] + b[d]
// 32x32 smem tile transpose. Reads of W coalesced along c, writes of Wt
// coalesced along d. Grid: (NUM_CLASSES/32, EMBED_DIM/32).
// ---------------------------------------------------------------------------
__global__ void transpose_bias_kernel(const float* __restrict__ W,
                                      const float* __restrict__ b) {
    __shared__ float tile[32][33];

    int c0 = blockIdx.x * 32;   // class-dim tile origin
    int d0 = blockIdx.y * 32;   // embed-dim tile origin

    int tx = threadIdx.x;       // 0..31
    int ty = threadIdx.y;       // 0..31

    // Read W[d0+ty][c0+tx] — coalesced in tx (contiguous classes)
    tile[ty][tx] = W[(size_t)(d0 + ty) * NUM_CLASSES + (c0 + tx)];
    __syncthreads();

    // Write Wt[c0+ty][d0+tx] = tile[tx][ty] + b[d0+tx] — coalesced in tx
    float bias = b[d0 + tx];
    g_Wt[(size_t)(c0 + ty) * EMBED_DIM + (d0 + tx)] = tile[tx][ty] + bias;
}

// ---------------------------------------------------------------------------
// Kernel 2: gather. One warp per token; each lane moves one float4 (16B),
// so a warp moves the full 512B embedding row, fully coalesced on both sides.
// Index is int32 (JAX without x64 silently downgrades jnp.int64 -> int32).
// Clamp defends against OOB if the dtype assumption is ever wrong.
// ---------------------------------------------------------------------------
__global__ void gather_kernel(const int* __restrict__ x,
                              float4* __restrict__ out) {
    int gid = blockIdx.x * blockDim.x + threadIdx.x;   // one float4 per thread
    int token = gid >> 5;       // 32 float4 per token (128 floats)
    int lane  = gid & 31;

    int idx = x[token];         // class index
    // Defensive clamp: wrong values beat illegal memory access.
    idx = min(max(idx, 0), NUM_CLASSES - 1);

    const float4* __restrict__ Wt4 = (const float4*)g_Wt;
    out[gid] = Wt4[(size_t)idx * 32 + lane];
}

extern "C" void kernel_launch(void* const* d_in, const int* in_sizes, int n_in,
                              void* d_out, int out_size) {
    const int*   x = (const int*)d_in[0];        // (64, 4096) int32
    const float* W = (const float*)d_in[1];      // (128, 32000) fp32
    const float* b = (const float*)d_in[2];      // (128,) fp32
    float4*    out = (float4*)d_out;             // (64, 4096, 128) fp32

    // Kernel 1: build Wt = W^T + b broadcast
    dim3 tgrid(NUM_CLASSES / 32, EMBED_DIM / 32);
    dim3 tblock(32, 32);
    transpose_bias_kernel<<<tgrid, tblock>>>(W, b);

    // Kernel 2: gather. Total threads = N_TOKENS * 32 (one float4 each).
    int threads = 256;
    int total = N_TOKENS * 32;
    gather_kernel<<<total / threads, threads>>>(x, out);
}

// round 3
// speedup vs baseline: 1.4983x; 1.4983x over previous
#include <cuda_runtime.h>
#include <cuda_bf16.h>
#include <cstdint>

// Problem shapes (fixed by the dataset)
#define NUM_CLASSES 32000
#define EMBED_DIM   128
#define N_TOKENS    (64 * 4096)            // B*T = 262144
#define TOTAL_F4    (N_TOKENS * 32)        // total float4 elements of output
#define UNROLL      4
#define G_STRIDE    (TOTAL_F4 / UNROLL)    // 2097152, multiple of 32

// Scratch: W^T with bias pre-added. 32000 * 128 * 4B = 16.384 MB.
__device__ float g_Wt[NUM_CLASSES * EMBED_DIM];

// ---------------------------------------------------------------------------
// Kernel 1: Wt[c][d] = W[d][c] + b[d]
// 32x32 smem tile, 32x8 threads, 4 elements per thread (MLP=4 before barrier).
// ---------------------------------------------------------------------------
__global__ void transpose_bias_kernel(const float* __restrict__ W,
                                      const float* __restrict__ b) {
    __shared__ float tile[32][33];

    int c0 = blockIdx.x * 32;   // class-dim tile origin
    int d0 = blockIdx.y * 32;   // embed-dim tile origin

    int tx = threadIdx.x;       // 0..31
    int ty = threadIdx.y;       // 0..7

    // Read W[d0+row][c0+tx] — coalesced in tx; 4 independent loads per thread.
    #pragma unroll
    for (int i = 0; i < 4; i++) {
        int row = ty + i * 8;
        tile[row][tx] = W[(size_t)(d0 + row) * NUM_CLASSES + (c0 + tx)];
    }
    __syncthreads();

    // Write Wt[c0+row][d0+tx] = tile[tx][row] + b[d0+tx] — coalesced in tx.
    float bias = b[d0 + tx];
    #pragma unroll
    for (int i = 0; i < 4; i++) {
        int row = ty + i * 8;
        g_Wt[(size_t)(c0 + row) * EMBED_DIM + (d0 + tx)] = tile[tx][row] + bias;
    }
}

// ---------------------------------------------------------------------------
// Kernel 2: gather with ILP=4. Each thread moves 4 float4s from 4 different
// tokens (positions separated by G_STRIDE, a multiple of 32, so warp
// coalescing of both the Wt read and the output write is preserved).
// Loads are batched: 4 index loads, then 4 payload loads, then 4 stores.
// ---------------------------------------------------------------------------
__global__ void gather_kernel(const int* __restrict__ x,
                              float4* __restrict__ out) {
    int gid  = blockIdx.x * blockDim.x + threadIdx.x;
    int lane = gid & 31;  // same lane offset for all 4 positions

    int g0 = gid;
    int g1 = gid + G_STRIDE;
    int g2 = gid + 2 * G_STRIDE;
    int g3 = gid + 3 * G_STRIDE;

    // 4 independent index loads (broadcast within warp, L1-cached)
    int i0 = x[g0 >> 5];
    int i1 = x[g1 >> 5];
    int i2 = x[g2 >> 5];
    int i3 = x[g3 >> 5];

    // Defensive clamp (wrong values beat illegal memory access)
    i0 = min(max(i0, 0), NUM_CLASSES - 1);
    i1 = min(max(i1, 0), NUM_CLASSES - 1);
    i2 = min(max(i2, 0), NUM_CLASSES - 1);
    i3 = min(max(i3, 0), NUM_CLASSES - 1);

    const float4* __restrict__ Wt4 = (const float4*)g_Wt;

    // 4 independent 16B loads in flight (MLP=4+)
    float4 v0 = Wt4[(size_t)i0 * 32 + lane];
    float4 v1 = Wt4[(size_t)i1 * 32 + lane];
    float4 v2 = Wt4[(size_t)i2 * 32 + lane];
    float4 v3 = Wt4[(size_t)i3 * 32 + lane];

    out[g0] = v0;
    out[g1] = v1;
    out[g2] = v2;
    out[g3] = v3;
}

extern "C" void kernel_launch(void* const* d_in, const int* in_sizes, int n_in,
                              void* d_out, int out_size) {
    const int*   x = (const int*)d_in[0];        // (64, 4096) int32
    const float* W = (const float*)d_in[1];      // (128, 32000) fp32
    const float* b = (const float*)d_in[2];      // (128,) fp32
    float4*    out = (float4*)d_out;             // (64, 4096, 128) fp32

    // Kernel 1: build Wt = W^T + b broadcast
    dim3 tgrid(NUM_CLASSES / 32, EMBED_DIM / 32);
    dim3 tblock(32, 8);
    transpose_bias_kernel<<<tgrid, tblock>>>(W, b);

    // Kernel 2: gather, ILP=4. Threads = TOTAL_F4 / UNROLL.
    int threads = 256;
    int total_threads = G_STRIDE;                // TOTAL_F4 / UNROLL
    gather_kernel<<<total_threads / threads, threads>>>(x, out);
}

// round 4
// speedup vs baseline: 1.8957x; 1.2652x over previous
#include <cuda_runtime.h>
#include <cuda_bf16.h>
#include <cstdint>

// Problem shapes (fixed by the dataset)
#define NUM_CLASSES 32000
#define EMBED_DIM   128
#define N_TOKENS    (64 * 4096)            // B*T = 262144
#define TOTAL_F4    (N_TOKENS * 32)        // total float4 elements of output
#define UNROLL      8
#define G_STRIDE    (TOTAL_F4 / UNROLL)    // 1048576, multiple of 32

// Scratch: W^T with bias pre-added. 32000 * 128 * 4B = 16.384 MB.
__device__ float g_Wt[NUM_CLASSES * EMBED_DIM];

// ---------------------------------------------------------------------------
// Kernel 1: Wt[c][d] = W[d][c] + b[d]
// Tile: 32 d-rows x 128 classes. 256 threads.
//   Load:  LDG.128 from W (fully coalesced, 4 per thread, MLP=4)
//   smem:  transposed scatter (4-way STS conflicts, hidden under LDG latency)
//   Store: one warp per class -> 128B coalesced STG.32 row, bias fused.
// Grid: (NUM_CLASSES/128, EMBED_DIM/32) = (250, 4).
// ---------------------------------------------------------------------------
__global__ void transpose_bias_kernel(const float* __restrict__ W,
                                      const float* __restrict__ b) {
    __shared__ float smemT[128][33];   // [class][d], stride 33 -> conflict-free reads

    int c0 = blockIdx.x * 128;  // class-dim tile origin
    int d0 = blockIdx.y * 32;   // embed-dim tile origin

    int t    = threadIdx.x;     // 0..255
    int lane = t & 31;
    int warp = t >> 5;          // 0..7

    // ---- Load phase: 4 float4 per thread from W, transposed into smem ----
    const float4* __restrict__ W4 = (const float4*)W;   // NUM_CLASSES/4 per row
    int cx = t & 31;            // float4 column within the 128-class tile
    #pragma unroll
    for (int i = 0; i < 4; i++) {
        int row = (t >> 5) + i * 8;          // d-row 0..31
        float4 v = W4[(size_t)(d0 + row) * (NUM_CLASSES / 4) + (c0 >> 2) + cx];
        smemT[4 * cx + 0][row] = v.x;
        smemT[4 * cx + 1][row] = v.y;
        smemT[4 * cx + 2][row] = v.z;
        smemT[4 * cx + 3][row] = v.w;
    }
    __syncthreads();

    // ---- Store phase: warp w writes classes w, w+8, ..., w+120 ----
    float bias = b[d0 + lane];
    #pragma unroll
    for (int i = 0; i < 16; i++) {
        int c = warp + i * 8;                // class within tile
        g_Wt[(size_t)(c0 + c) * EMBED_DIM + (d0 + lane)] = smemT[c][lane] + bias;
    }
}

// ---------------------------------------------------------------------------
// Kernel 2: gather with ILP=8. Each thread moves 8 float4s from 8 tokens
// (positions separated by G_STRIDE, a multiple of 32 -> coalescing preserved).
//   - Wt reads via __ldcg: L2-only. 16MB table can't live in L1; skipping L1
//     saves L1tex wavefront bandwidth (the 60.6% pipe last round).
//   - out stores via __stcs: streaming/evict-first, so the 128MB output
//     stream doesn't evict Wt from L2 (keeps table reads off DRAM).
// ---------------------------------------------------------------------------
__global__ void gather_kernel(const int* __restrict__ x,
                              float4* __restrict__ out) {
    int gid  = blockIdx.x * blockDim.x + threadIdx.x;
    int lane = gid & 31;  // same lane offset for all 8 positions

    int g[UNROLL];
    int idx[UNROLL];
    #pragma unroll
    for (int i = 0; i < UNROLL; i++) g[i] = gid + i * G_STRIDE;

    // 8 independent index loads (warp-uniform broadcast)
    #pragma unroll
    for (int i = 0; i < UNROLL; i++) {
        int v = x[g[i] >> 5];
        idx[i] = min(max(v, 0), NUM_CLASSES - 1);  // defensive clamp
    }

    const float4* __restrict__ Wt4 = (const float4*)g_Wt;

    // 8 independent 16B loads in flight (L2-only)
    float4 v[UNROLL];
    #pragma unroll
    for (int i = 0; i < UNROLL; i++)
        v[i] = __ldcg(&Wt4[(size_t)idx[i] * 32 + lane]);

    // streaming stores
    #pragma unroll
    for (int i = 0; i < UNROLL; i++)
        __stcs(&out[g[i]], v[i]);
}

extern "C" void kernel_launch(void* const* d_in, const int* in_sizes, int n_in,
                              void* d_out, int out_size) {
    const int*   x = (const int*)d_in[0];        // (64, 4096) int32
    const float* W = (const float*)d_in[1];      // (128, 32000) fp32
    const float* b = (const float*)d_in[2];      // (128,) fp32
    float4*    out = (float4*)d_out;             // (64, 4096, 128) fp32

    // Kernel 1: build Wt = W^T + b broadcast
    dim3 tgrid(NUM_CLASSES / 128, EMBED_DIM / 32);
    transpose_bias_kernel<<<tgrid, 256>>>(W, b);

    // Kernel 2: gather, ILP=8. Threads = TOTAL_F4 / UNROLL.
    int threads = 256;
    gather_kernel<<<G_STRIDE / threads, threads>>>(x, out);
}